// round 14
// baseline (speedup 1.0000x reference)
#include <cuda_runtime.h>
#include <cuda_fp16.h>
#include <math.h>
#include <stdint.h>

#define FULLMASK 0xffffffffu

constexpr int BATCH = 4, L = 2048, DM = 1024, DI = 2048, E2 = 4096;
constexpr int DR = 64, DS = 16, XD = 96; // XD = DR + 2*DS
constexpr int KSPL = 4;                  // split-K factor for x_dbl GEMM

// ---- scratch (device globals; no runtime allocation) ----
__device__ float  g_xz   [(size_t)BATCH * L * E2];   // in-proj out (f32): x | z
__device__ float  g_xc   [(size_t)BATCH * L * DI];   // conv out, exact (scan)
__device__ __half g_xc_h [(size_t)BATCH * L * DI];   // conv out fp16 (xdbl GEMM A)
__device__ float  g_xdbl [(size_t)BATCH * L * XD];   // dt_low|B|C f32 (scan B/C)
__device__ __half g_xdblh[(size_t)BATCH * L * XD];   // fp16 copy (dt GEMM A)
__device__ float  g_xdbl_p[(size_t)KSPL * BATCH * L * XD]; // split-K partials
__device__ float  g_delta[(size_t)BATCH * L * DI];   // softplus(dt+b_dt) (scan)
__device__ __half g_y_h  [(size_t)BATCH * L * DI];   // gated scan out fp16
// fp16 copies of external operands
__device__ __half g_h_h   [(size_t)BATCH * L * DM];
__device__ __half g_win_h [(size_t)E2 * DM];
__device__ __half g_wx_h  [(size_t)XD * DI];
__device__ __half g_wdt_h [(size_t)DI * DR];
__device__ __half g_wout_h[(size_t)DM * DI];

__device__ __forceinline__ float sigmoidf_(float x) { return 1.f / (1.f + __expf(-x)); }

__device__ __forceinline__ float ex2_(float x) {
    float r; asm("ex2.approx.f32 %0, %1;" : "=f"(r) : "f"(x)); return r;
}

__device__ __forceinline__ void mma_f16(float c[4], const uint32_t a[4], const uint32_t b[2]) {
    asm volatile(
        "mma.sync.aligned.m16n8k16.row.col.f32.f16.f16.f32 "
        "{%0,%1,%2,%3}, {%4,%5,%6,%7}, {%8,%9}, {%0,%1,%2,%3};"
        : "+f"(c[0]), "+f"(c[1]), "+f"(c[2]), "+f"(c[3])
        : "r"(a[0]), "r"(a[1]), "r"(a[2]), "r"(a[3]), "r"(b[0]), "r"(b[1]));
}

__device__ __forceinline__ uint2 cvt4(float4 v) {
    __half2 h0 = __floats2half2_rn(v.x, v.y);
    __half2 h1 = __floats2half2_rn(v.z, v.w);
    uint2 pk;
    pk.x = *reinterpret_cast<uint32_t*>(&h0);
    pk.y = *reinterpret_cast<uint32_t*>(&h1);
    return pk;
}

// =====================================================================
// f32 -> f16 conversion kernels
// =====================================================================
__global__ __launch_bounds__(256)
void cvt_f16(const float* __restrict__ in, __half* __restrict__ out, int n4)
{
    const int i = blockIdx.x * blockDim.x + threadIdx.x;
    if (i < n4)
        reinterpret_cast<uint2*>(out)[i] = cvt4(reinterpret_cast<const float4*>(in)[i]);
}

__global__ __launch_bounds__(256)
void cvt_f16x3(const float* __restrict__ s0, __half* __restrict__ d0, int n0,
               const float* __restrict__ s1, __half* __restrict__ d1, int n1,
               const float* __restrict__ s2, __half* __restrict__ d2, int n2)
{
    int i = blockIdx.x * blockDim.x + threadIdx.x;
    if (i < n0) {
        reinterpret_cast<uint2*>(d0)[i] = cvt4(reinterpret_cast<const float4*>(s0)[i]);
        return;
    }
    i -= n0;
    if (i < n1) {
        reinterpret_cast<uint2*>(d1)[i] = cvt4(reinterpret_cast<const float4*>(s1)[i]);
        return;
    }
    i -= n1;
    if (i < n2)
        reinterpret_cast<uint2*>(d2)[i] = cvt4(reinterpret_cast<const float4*>(s2)[i]);
}

// =====================================================================
// Shared GEMM constants (padded 144B SMEM rows, BK=64)
// =====================================================================
constexpr int HROW  = 144;                  // bytes per SMEM row (64 fp16 + 16 pad)

// ---- small GEMM: 128x128x64, 8 warps (2x4), warp tile 64x32, 2 CTA/SM ----
constexpr int HASTG = 128 * HROW;           // 18432 B per operand stage
constexpr int HSTG  = 2 * HASTG;            // 36864 B per stage
constexpr int HSMEM = 3 * HSTG;             // 110592 B

// ---- big GEMM: 128x256x64, 8 warps (2x4), warp tile 64x64, 1 CTA/SM ----
constexpr int GASTG = 128 * HROW;           // A stage: 18432 B
constexpr int GBSTG = 256 * HROW;           // B stage: 36864 B
constexpr int GSTG  = GASTG + GBSTG;        // 55296 B per stage
constexpr int GSMEM = 3 * GSTG;             // 165888 B

// =====================================================================
// Small fp16 tensor GEMM (TN). EPI: 0 plain, 1 softplus(v+bias[n]).
// GN guards B rows (N=96). SPLITK via blockIdx.z.
// =====================================================================
template<int EPI, bool GN, bool SPLITK>
__global__ __launch_bounds__(256, 2)
void h_gemm(const __half* __restrict__ A, int lda,
            const __half* __restrict__ Bw, int ldb,
            float* __restrict__ C, int ldc,
            int K, int N, const float* __restrict__ bias)
{
    extern __shared__ __align__(16) char smraw[];
    const uint32_t sbase = (uint32_t)__cvta_generic_to_shared(smraw);

    if (SPLITK) {
        const size_t kz = (size_t)blockIdx.z;
        A  += kz * K;
        Bw += kz * K;
        C  += kz * (size_t)gridDim.y * 128 * ldc;
    }

    const int tid  = threadIdx.x;
    const int warp = tid >> 5;
    const int lane = tid & 31;
    const int g    = lane >> 2;
    const int t4   = lane & 3;
    const int mw   = (warp >> 2) * 64;
    const int nw   = (warp & 3) * 32;

    const __half* Ab = A  + (size_t)blockIdx.y * 128 * lda;
    const __half* Bb = Bw + (size_t)blockIdx.x * 128 * ldb;
    const int nBase = blockIdx.x * 128;
    const int nt = K / 64;

    const int q  = lane >> 3;
    const int rr = lane & 7;
    const int lmRow = (q & 1) * 8 + rr;
    const int lmCol = (q >> 1) * 16;

    int cr[4], cc[4];
    #pragma unroll
    for (int u = 0; u < 4; ++u) { int idx = tid + u * 256; cr[u] = idx >> 3; cc[u] = idx & 7; }

    auto loadStage = [&](int t, int s) {
        const int k0 = t * 64;
        const uint32_t aS = sbase + s * HSTG;
        const uint32_t bS = aS + HASTG;
        #pragma unroll
        for (int u = 0; u < 4; ++u) {
            const __half* src = Ab + (size_t)cr[u] * lda + k0 + cc[u] * 8;
            uint32_t dst = aS + (uint32_t)(cr[u] * HROW + cc[u] * 16);
            asm volatile("cp.async.cg.shared.global [%0], [%1], 16;" :: "r"(dst), "l"(src));
        }
        #pragma unroll
        for (int u = 0; u < 4; ++u) {
            uint32_t dst = bS + (uint32_t)(cr[u] * HROW + cc[u] * 16);
            if (GN) {
                const bool ok = (nBase + cr[u]) < N;
                const __half* src = Bb + (size_t)(ok ? cr[u] : 0) * ldb + k0 + cc[u] * 8;
                const int sz = ok ? 16 : 0;
                asm volatile("cp.async.cg.shared.global [%0], [%1], 16, %2;"
                             :: "r"(dst), "l"(src), "r"(sz));
            } else {
                const __half* src = Bb + (size_t)cr[u] * ldb + k0 + cc[u] * 8;
                asm volatile("cp.async.cg.shared.global [%0], [%1], 16;" :: "r"(dst), "l"(src));
            }
        }
    };

    float acc[4][4][4];
    #pragma unroll
    for (int i = 0; i < 4; ++i)
        #pragma unroll
        for (int j = 0; j < 4; ++j)
            #pragma unroll
            for (int r = 0; r < 4; ++r) acc[i][j][r] = 0.f;

    #pragma unroll
    for (int t = 0; t < 2; ++t) {
        if (t < nt) loadStage(t, t);
        asm volatile("cp.async.commit_group;");
    }

    for (int t = 0; t < nt; ++t) {
        asm volatile("cp.async.wait_group 1;");
        __syncthreads();
        if (t + 2 < nt) loadStage(t + 2, (t + 2) % 3);
        asm volatile("cp.async.commit_group;");

        const int s = t % 3;
        const uint32_t aS = sbase + s * HSTG;
        const uint32_t bS = aS + HASTG;

        #pragma unroll
        for (int kk = 0; kk < 4; ++kk) {
            uint32_t af[4][4], bf[4][2];
            #pragma unroll
            for (int i = 0; i < 4; ++i) {
                const uint32_t ad = aS + (uint32_t)((mw + i * 16 + lmRow) * HROW + kk * 32 + lmCol);
                asm volatile("ldmatrix.sync.aligned.m8n8.x4.shared.b16 {%0,%1,%2,%3}, [%4];"
                    : "=r"(af[i][0]), "=r"(af[i][1]), "=r"(af[i][2]), "=r"(af[i][3])
                    : "r"(ad));
            }
            #pragma unroll
            for (int jj = 0; jj < 2; ++jj) {
                const uint32_t bd = bS + (uint32_t)((nw + jj * 16 + lmRow) * HROW + kk * 32 + lmCol);
                asm volatile("ldmatrix.sync.aligned.m8n8.x4.shared.b16 {%0,%1,%2,%3}, [%4];"
                    : "=r"(bf[2*jj][0]), "=r"(bf[2*jj+1][0]), "=r"(bf[2*jj][1]), "=r"(bf[2*jj+1][1])
                    : "r"(bd));
            }
            #pragma unroll
            for (int i = 0; i < 4; ++i)
                #pragma unroll
                for (int j = 0; j < 4; ++j)
                    mma_f16(acc[i][j], af[i], bf[j]);
        }
    }

    #pragma unroll
    for (int i = 0; i < 4; ++i) {
        const int m = blockIdx.y * 128 + mw + i * 16 + g;
        #pragma unroll
        for (int j = 0; j < 4; ++j) {
            const int n = nBase + nw + j * 8 + t4 * 2;
            if (GN && n + 2 > N) continue;
            float v0 = acc[i][j][0], v1 = acc[i][j][1];
            float v2 = acc[i][j][2], v3 = acc[i][j][3];
            if (EPI == 1) {
                const float b0v = bias[n], b1v = bias[n + 1];
                v0 += b0v; v1 += b1v; v2 += b0v; v3 += b1v;
                v0 = (v0 > 20.f) ? v0 : log1pf(__expf(v0));
                v1 = (v1 > 20.f) ? v1 : log1pf(__expf(v1));
                v2 = (v2 > 20.f) ? v2 : log1pf(__expf(v2));
                v3 = (v3 > 20.f) ? v3 : log1pf(__expf(v3));
            }
            *reinterpret_cast<float2*>(&C[(size_t)m * ldc + n])       = make_float2(v0, v1);
            *reinterpret_cast<float2*>(&C[(size_t)(m + 8) * ldc + n]) = make_float2(v2, v3);
        }
    }
}

// =====================================================================
// Big fp16 tensor GEMM (TN): CTA 128x256x64, 8 warps (2x4), warp tile
// 64x64 (HMMA:LDSM = 4:1), 3-stage cp.async, 1 CTA/SM. Plain f32 store.
// Used for in-proj and out-proj (M%128==0, N%256==0, K%64==0).
// =====================================================================
__global__ __launch_bounds__(256, 1)
void h_gemm_big(const __half* __restrict__ A, int lda,
                const __half* __restrict__ Bw, int ldb,
                float* __restrict__ C, int ldc, int K)
{
    extern __shared__ __align__(16) char smraw[];
    const uint32_t sbase = (uint32_t)__cvta_generic_to_shared(smraw);

    const int tid  = threadIdx.x;
    const int warp = tid >> 5;
    const int lane = tid & 31;
    const int g    = lane >> 2;
    const int t4   = lane & 3;
    const int mw   = (warp >> 2) * 64;   // 2 M-tiles of 64
    const int nw   = (warp & 3) * 64;    // 4 N-tiles of 64

    const __half* Ab = A  + (size_t)blockIdx.y * 128 * lda;
    const __half* Bb = Bw + (size_t)blockIdx.x * 256 * ldb;
    const int nBase = blockIdx.x * 256;
    const int nt = K / 64;

    const int q  = lane >> 3;
    const int rr = lane & 7;
    const int lmRow = (q & 1) * 8 + rr;
    const int lmCol = (q >> 1) * 16;

    // cp.async: A 1024 chunks (4/thread), B 2048 chunks (8/thread)
    int cr[4], cc[4];
    #pragma unroll
    for (int u = 0; u < 4; ++u) { int idx = tid + u * 256; cr[u] = idx >> 3; cc[u] = idx & 7; }

    auto loadStage = [&](int t, int s) {
        const int k0 = t * 64;
        const uint32_t aS = sbase + s * GSTG;
        const uint32_t bS = aS + GASTG;
        #pragma unroll
        for (int u = 0; u < 4; ++u) {
            const __half* src = Ab + (size_t)cr[u] * lda + k0 + cc[u] * 8;
            uint32_t dst = aS + (uint32_t)(cr[u] * HROW + cc[u] * 16);
            asm volatile("cp.async.cg.shared.global [%0], [%1], 16;" :: "r"(dst), "l"(src));
        }
        #pragma unroll
        for (int u = 0; u < 8; ++u) {
            int idx = tid + u * 256; int r = idx >> 3, c = idx & 7;
            const __half* src = Bb + (size_t)r * ldb + k0 + c * 8;
            uint32_t dst = bS + (uint32_t)(r * HROW + c * 16);
            asm volatile("cp.async.cg.shared.global [%0], [%1], 16;" :: "r"(dst), "l"(src));
        }
    };

    float acc[4][8][4];
    #pragma unroll
    for (int i = 0; i < 4; ++i)
        #pragma unroll
        for (int j = 0; j < 8; ++j)
            #pragma unroll
            for (int r = 0; r < 4; ++r) acc[i][j][r] = 0.f;

    #pragma unroll
    for (int t = 0; t < 2; ++t) {
        if (t < nt) loadStage(t, t);
        asm volatile("cp.async.commit_group;");
    }

    for (int t = 0; t < nt; ++t) {
        asm volatile("cp.async.wait_group 1;");
        __syncthreads();
        if (t + 2 < nt) loadStage(t + 2, (t + 2) % 3);
        asm volatile("cp.async.commit_group;");

        const int s = t % 3;
        const uint32_t aS = sbase + s * GSTG;
        const uint32_t bS = aS + GASTG;

        #pragma unroll
        for (int kk = 0; kk < 4; ++kk) {
            uint32_t af[4][4], bf[8][2];
            #pragma unroll
            for (int i = 0; i < 4; ++i) {
                const uint32_t ad = aS + (uint32_t)((mw + i * 16 + lmRow) * HROW + kk * 32 + lmCol);
                asm volatile("ldmatrix.sync.aligned.m8n8.x4.shared.b16 {%0,%1,%2,%3}, [%4];"
                    : "=r"(af[i][0]), "=r"(af[i][1]), "=r"(af[i][2]), "=r"(af[i][3])
                    : "r"(ad));
            }
            #pragma unroll
            for (int jj = 0; jj < 4; ++jj) {
                const uint32_t bd = bS + (uint32_t)((nw + jj * 16 + lmRow) * HROW + kk * 32 + lmCol);
                asm volatile("ldmatrix.sync.aligned.m8n8.x4.shared.b16 {%0,%1,%2,%3}, [%4];"
                    : "=r"(bf[2*jj][0]), "=r"(bf[2*jj+1][0]), "=r"(bf[2*jj][1]), "=r"(bf[2*jj+1][1])
                    : "r"(bd));
            }
            #pragma unroll
            for (int i = 0; i < 4; ++i)
                #pragma unroll
                for (int j = 0; j < 8; ++j)
                    mma_f16(acc[i][j], af[i], bf[j]);
        }
    }

    #pragma unroll
    for (int i = 0; i < 4; ++i) {
        const int m = blockIdx.y * 128 + mw + i * 16 + g;
        #pragma unroll
        for (int j = 0; j < 8; ++j) {
            const int n = nBase + nw + j * 8 + t4 * 2;
            *reinterpret_cast<float2*>(&C[(size_t)m * ldc + n]) =
                make_float2(acc[i][j][0], acc[i][j][1]);
            *reinterpret_cast<float2*>(&C[(size_t)(m + 8) * ldc + n]) =
                make_float2(acc[i][j][2], acc[i][j][3]);
        }
    }
}

// =====================================================================
// split-K reduction for x_dbl: sums KSPL partials -> f32 + fp16
// =====================================================================
__global__ __launch_bounds__(256)
void reduce_xdbl(int n4)
{
    const int i = blockIdx.x * blockDim.x + threadIdx.x;
    if (i >= n4) return;
    const size_t stride4 = (size_t)BATCH * L * XD / 4;
    const float4* p = reinterpret_cast<const float4*>(g_xdbl_p);
    float4 a = p[i], b = p[i + stride4], c = p[i + 2 * stride4], d = p[i + 3 * stride4];
    float4 s;
    s.x = (a.x + b.x) + (c.x + d.x);
    s.y = (a.y + b.y) + (c.y + d.y);
    s.z = (a.z + b.z) + (c.z + d.z);
    s.w = (a.w + b.w) + (c.w + d.w);
    reinterpret_cast<float4*>(g_xdbl)[i] = s;
    reinterpret_cast<uint2*>(g_xdblh)[i] = cvt4(s);
}

// =====================================================================
// Dual dilated causal depthwise conv + silu + softmax gate.
// =====================================================================
__global__ __launch_bounds__(256)
void conv_kernel(const float* __restrict__ w1, const float* __restrict__ b1,
                 const float* __restrict__ w2, const float* __restrict__ b2,
                 const float* __restrict__ gates)
{
    const int tid = blockIdx.x * blockDim.x + threadIdx.x;
    const int d    = tid % DI;
    const int rest = tid / DI;
    const int lc   = rest % (L / 16);
    const int b    = rest / (L / 16);
    const int l0   = lc * 16;

    const float* xp = g_xz + (size_t)b * L * E2 + d;
    const size_t obase = (size_t)b * L * DI + d;

    const float w10 = w1[d*4+0], w11 = w1[d*4+1], w12 = w1[d*4+2], w13 = w1[d*4+3];
    const float w20 = w2[d*4+0], w21 = w2[d*4+1], w22 = w2[d*4+2], w23 = w2[d*4+3];
    const float b1v = b1[d], b2v = b2[d];
    const float e0 = __expf(gates[0]), e1 = __expf(gates[1]);
    const float gden = 1.f / (e0 + e1);
    const float g0 = e0 * gden, g1 = e1 * gden;

    float xb[22];
    #pragma unroll
    for (int i = 0; i < 22; ++i) {
        const int l = l0 - 6 + i;
        xb[i] = (l >= 0) ? xp[(size_t)l * E2] : 0.f;
    }
    #pragma unroll
    for (int i = 0; i < 16; ++i) {
        const float x0  = xb[i+6], xm1 = xb[i+5], xm2 = xb[i+4];
        const float xm3 = xb[i+3], xm4 = xb[i+2], xm6 = xb[i+0];
        const float c1 = fmaf(w13, x0, fmaf(w12, xm1, fmaf(w11, xm2, fmaf(w10, xm3, b1v))));
        const float c2 = fmaf(w23, x0, fmaf(w22, xm2, fmaf(w21, xm4, fmaf(w20, xm6, b2v))));
        const float s1 = c1 * sigmoidf_(c1);
        const float s2 = c2 * sigmoidf_(c2);
        const float v  = fmaf(g0, s1, g1 * s2);
        g_xc  [obase + (size_t)(l0 + i) * DI] = v;
        g_xc_h[obase + (size_t)(l0 + i) * DI] = __float2half_rn(v);
    }
}

// =====================================================================
// Selective scan + D-skip + silu(z) gate, SMEM-staged operands.
// 8 lanes per channel, 2 states per lane (n, n+8); warp = 4 channels.
// =====================================================================
constexpr int CH  = 16;   // timesteps per chunk
constexpr int CPB = 32;   // channels per block
__global__ __launch_bounds__(256)
void scan_kernel(const float* __restrict__ A_log, const float* __restrict__ D_param)
{
    __shared__ float sd [2][CH][CPB];   // delta
    __shared__ float sxv[2][CH][CPB];   // xc
    __shared__ float szv[2][CH][CPB];   // z
    __shared__ float sbc[2][CH][32];    // B(16) | C(16), channel-independent

    const int tid   = threadIdx.x;
    const int warp  = tid >> 5;
    const int lane  = tid & 31;
    const int grp   = lane >> 3;
    const int n     = lane & 7;
    const int ch    = warp * 4 + grp;
    const int blk   = blockIdx.x;
    const int b     = blk >> 6;
    const int dbase = (blk & 63) * CPB;
    const int d     = dbase + ch;

    const float LG2E = 1.4426950408889634f;
    const float Ac0 = -__expf(A_log[d * DS + n])     * LG2E;
    const float Ac1 = -__expf(A_log[d * DS + n + 8]) * LG2E;
    const float Dv  = D_param[d];

    const int srow = tid >> 4;
    const int sc2  = (tid & 15) * 2;
    const size_t mb = (size_t)b * L;

    auto stage = [&](int c, int buf) {
        const int l = c * CH + srow;
        float2 t;
        t = *reinterpret_cast<const float2*>(g_delta + (mb + l) * DI + dbase + sc2);
        sd [buf][srow][sc2] = t.x; sd [buf][srow][sc2 + 1] = t.y;
        t = *reinterpret_cast<const float2*>(g_xc + (mb + l) * DI + dbase + sc2);
        sxv[buf][srow][sc2] = t.x; sxv[buf][srow][sc2 + 1] = t.y;
        t = *reinterpret_cast<const float2*>(g_xz + (mb + l) * E2 + DI + dbase + sc2);
        szv[buf][srow][sc2] = t.x; szv[buf][srow][sc2 + 1] = t.y;
        t = *reinterpret_cast<const float2*>(g_xdbl + (mb + l) * XD + DR + sc2);
        sbc[buf][srow][sc2] = t.x; sbc[buf][srow][sc2 + 1] = t.y;
    };

    stage(0, 0);
    __syncthreads();

    __half* yp = g_y_h + mb * DI + d;
    float h0 = 0.f, h1 = 0.f;

    for (int c = 0; c < L / CH; ++c) {
        const int buf = c & 1;
        if (c + 1 < L / CH) stage(c + 1, buf ^ 1);

        const int lbase = c * CH;
        #pragma unroll
        for (int i = 0; i < CH; ++i) {
            const float dlt = sd [buf][i][ch];
            const float xv  = sxv[buf][i][ch];
            const float zv  = szv[buf][i][ch];
            const float B0  = sbc[buf][i][n];
            const float B1  = sbc[buf][i][n + 8];
            const float C0  = sbc[buf][i][16 + n];
            const float C1  = sbc[buf][i][24 + n];

            const float dA0 = ex2_(dlt * Ac0);
            const float dA1 = ex2_(dlt * Ac1);
            const float tt  = dlt * xv;
            h0 = fmaf(h0, dA0, tt * B0);
            h1 = fmaf(h1, dA1, tt * B1);

            float v = fmaf(h1, C1, h0 * C0);
            v += __shfl_xor_sync(FULLMASK, v, 1);
            v += __shfl_xor_sync(FULLMASK, v, 2);
            v += __shfl_xor_sync(FULLMASK, v, 4);

            if (n == 0) {
                const float y = fmaf(Dv, xv, v);
                yp[(size_t)(lbase + i) * DI] = __float2half_rn(y * (zv * sigmoidf_(zv)));
            }
        }
        __syncthreads();
    }
}

// =====================================================================
extern "C" void kernel_launch(void* const* d_in, const int* in_sizes, int n_in,
                              void* d_out, int out_size)
{
    const float* hidden     = (const float*)d_in[0];
    const float* W_in       = (const float*)d_in[1];
    const float* conv_w1    = (const float*)d_in[2];
    const float* conv_b1    = (const float*)d_in[3];
    const float* conv_w2    = (const float*)d_in[4];
    const float* conv_b2    = (const float*)d_in[5];
    const float* conv_gates = (const float*)d_in[6];
    const float* W_x        = (const float*)d_in[7];
    const float* W_dt       = (const float*)d_in[8];
    const float* b_dt       = (const float*)d_in[9];
    const float* A_log      = (const float*)d_in[10];
    const float* D_param    = (const float*)d_in[11];
    const float* W_out      = (const float*)d_in[12];
    float*       out        = (float*)d_out;

    float  *p_xz, *p_xdbl_p, *p_delta;
    __half *p_xch, *p_xdblh, *p_yh, *p_h, *p_win, *p_wx, *p_wdt, *p_wout;
    cudaGetSymbolAddress((void**)&p_xz,     g_xz);
    cudaGetSymbolAddress((void**)&p_xdbl_p, g_xdbl_p);
    cudaGetSymbolAddress((void**)&p_delta,  g_delta);
    cudaGetSymbolAddress((void**)&p_xch,    g_xc_h);
    cudaGetSymbolAddress((void**)&p_xdblh,  g_xdblh);
    cudaGetSymbolAddress((void**)&p_yh,     g_y_h);
    cudaGetSymbolAddress((void**)&p_h,      g_h_h);
    cudaGetSymbolAddress((void**)&p_win,    g_win_h);
    cudaGetSymbolAddress((void**)&p_wx,     g_wx_h);
    cudaGetSymbolAddress((void**)&p_wdt,    g_wdt_h);
    cudaGetSymbolAddress((void**)&p_wout,   g_wout_h);

    static bool attr_done = false;
    if (!attr_done) {
        cudaFuncSetAttribute((const void*)h_gemm<0,false,false>,
                             cudaFuncAttributeMaxDynamicSharedMemorySize, HSMEM);
        cudaFuncSetAttribute((const void*)h_gemm<1,false,false>,
                             cudaFuncAttributeMaxDynamicSharedMemorySize, HSMEM);
        cudaFuncSetAttribute((const void*)h_gemm<0,true,true>,
                             cudaFuncAttributeMaxDynamicSharedMemorySize, HSMEM);
        cudaFuncSetAttribute((const void*)h_gemm_big,
                             cudaFuncAttributeMaxDynamicSharedMemorySize, GSMEM);
        attr_done = true;
    }

    const int M = BATCH * L;   // 8192

    // [0] cvt hidden, [1] cvt W_in, [2] fused cvt of W_out/W_x/W_dt
    {
        int n4h = (int)((size_t)BATCH * L * DM / 4);
        cvt_f16<<<(n4h + 255) / 256, 256>>>(hidden, p_h, n4h);
        int n4w = (int)((size_t)E2 * DM / 4);
        cvt_f16<<<(n4w + 255) / 256, 256>>>(W_in, p_win, n4w);
        int n0 = (int)((size_t)DM * DI / 4);
        int n1 = (int)((size_t)XD * DI / 4);
        int n2 = (int)((size_t)DI * DR / 4);
        cvt_f16x3<<<(n0 + n1 + n2 + 255) / 256, 256>>>(
            W_out, p_wout, n0, W_x, p_wx, n1, W_dt, p_wdt, n2);
    }

    // [3] in-proj (big tile): (M=8192, N=4096, K=1024)
    h_gemm_big<<<dim3(E2/256, M/128), 256, GSMEM>>>(
        p_h, DM, p_win, DM, p_xz, E2, DM);

    // [4] dwconv + silu + gate -> g_xc (f32) + g_xc_h (fp16)
    conv_kernel<<<(BATCH * (L/16) * DI) / 256, 256>>>(
        conv_w1, conv_b1, conv_w2, conv_b2, conv_gates);

    // [5] x_dbl split-K: (M=8192, N=96, K=2048/4 per slice)
    h_gemm<0,true,true><<<dim3(1, M/128, KSPL), 256, HSMEM>>>(
        p_xch, DI, p_wx, DI, p_xdbl_p, XD, DI / KSPL, XD, nullptr);

    // [6] reduce partials -> g_xdbl (f32) + g_xdblh (fp16)
    {
        int n4 = (int)((size_t)BATCH * L * XD / 4);
        reduce_xdbl<<<(n4 + 255) / 256, 256>>>(n4);
    }

    // [7] delta = softplus(dt_low . W_dt^T + b_dt): (M=8192, N=2048, K=64)
    h_gemm<1,false,false><<<dim3(DI/128, M/128), 256, HSMEM>>>(
        p_xdblh, XD, p_wdt, DR, p_delta, DI, DR, DI, b_dt);

    // [8] selective scan -> g_y_h (fp16)
    scan_kernel<<<BATCH * (DI / CPB), 256>>>(A_log, D_param);

    // [9] out-proj (big tile): (M=8192, N=1024, K=2048)
    h_gemm_big<<<dim3(DM/256, M/128), 256, GSMEM>>>(
        p_yh, DI, p_wout, DI, out, DM, DI);
}

// round 15
// speedup vs baseline: 1.0318x; 1.0318x over previous
#include <cuda_runtime.h>
#include <cuda_fp16.h>
#include <math.h>
#include <stdint.h>

#define FULLMASK 0xffffffffu

constexpr int BATCH = 4, L = 2048, DM = 1024, DI = 2048, E2 = 4096;
constexpr int DR = 64, DS = 16, XD = 96; // XD = DR + 2*DS
constexpr int KSPL = 4;                  // split-K factor for x_dbl GEMM

// ---- scratch (device globals; no runtime allocation) ----
__device__ __half g_xz_h [(size_t)BATCH * L * E2];   // in-proj out fp16: x | z
__device__ float  g_xc   [(size_t)BATCH * L * DI];   // conv out f32 (scan)
__device__ __half g_xc_h [(size_t)BATCH * L * DI];   // conv out fp16 (xdbl GEMM A)
__device__ float  g_xdbl [(size_t)BATCH * L * XD];   // dt_low|B|C f32 (scan B/C)
__device__ __half g_xdblh[(size_t)BATCH * L * XD];   // fp16 copy (dt GEMM A)
__device__ float  g_xdbl_p[(size_t)KSPL * BATCH * L * XD]; // split-K partials
__device__ float  g_delta[(size_t)BATCH * L * DI];   // softplus(dt+b_dt) (scan)
__device__ __half g_y_h  [(size_t)BATCH * L * DI];   // gated scan out fp16
// fp16 copies of external operands
__device__ __half g_h_h   [(size_t)BATCH * L * DM];
__device__ __half g_win_h [(size_t)E2 * DM];
__device__ __half g_wx_h  [(size_t)XD * DI];
__device__ __half g_wdt_h [(size_t)DI * DR];
__device__ __half g_wout_h[(size_t)DM * DI];

__device__ __forceinline__ float sigmoidf_(float x) { return 1.f / (1.f + __expf(-x)); }

__device__ __forceinline__ float ex2_(float x) {
    float r; asm("ex2.approx.f32 %0, %1;" : "=f"(r) : "f"(x)); return r;
}
__device__ __forceinline__ float lg2_(float x) {
    float r; asm("lg2.approx.f32 %0, %1;" : "=f"(r) : "f"(x)); return r;
}
// softplus via MUFU: log(1+e^v) = ln2 * lg2(1 + 2^(v*log2e))
__device__ __forceinline__ float softplus_(float v) {
    const float LG2E = 1.4426950408889634f, LN2 = 0.6931471805599453f;
    return (v > 20.f) ? v : LN2 * lg2_(1.f + ex2_(v * LG2E));
}

__device__ __forceinline__ void mma_f16(float c[4], const uint32_t a[4], const uint32_t b[2]) {
    asm volatile(
        "mma.sync.aligned.m16n8k16.row.col.f32.f16.f16.f32 "
        "{%0,%1,%2,%3}, {%4,%5,%6,%7}, {%8,%9}, {%0,%1,%2,%3};"
        : "+f"(c[0]), "+f"(c[1]), "+f"(c[2]), "+f"(c[3])
        : "r"(a[0]), "r"(a[1]), "r"(a[2]), "r"(a[3]), "r"(b[0]), "r"(b[1]));
}

__device__ __forceinline__ uint2 cvt4(float4 v) {
    __half2 h0 = __floats2half2_rn(v.x, v.y);
    __half2 h1 = __floats2half2_rn(v.z, v.w);
    uint2 pk;
    pk.x = *reinterpret_cast<uint32_t*>(&h0);
    pk.y = *reinterpret_cast<uint32_t*>(&h1);
    return pk;
}

// =====================================================================
// f32 -> f16 conversion kernels
// =====================================================================
__global__ __launch_bounds__(256)
void cvt_f16(const float* __restrict__ in, __half* __restrict__ out, int n4)
{
    const int i = blockIdx.x * blockDim.x + threadIdx.x;
    if (i < n4)
        reinterpret_cast<uint2*>(out)[i] = cvt4(reinterpret_cast<const float4*>(in)[i]);
}

__global__ __launch_bounds__(256)
void cvt_f16x3(const float* __restrict__ s0, __half* __restrict__ d0, int n0,
               const float* __restrict__ s1, __half* __restrict__ d1, int n1,
               const float* __restrict__ s2, __half* __restrict__ d2, int n2)
{
    int i = blockIdx.x * blockDim.x + threadIdx.x;
    if (i < n0) {
        reinterpret_cast<uint2*>(d0)[i] = cvt4(reinterpret_cast<const float4*>(s0)[i]);
        return;
    }
    i -= n0;
    if (i < n1) {
        reinterpret_cast<uint2*>(d1)[i] = cvt4(reinterpret_cast<const float4*>(s1)[i]);
        return;
    }
    i -= n1;
    if (i < n2)
        reinterpret_cast<uint2*>(d2)[i] = cvt4(reinterpret_cast<const float4*>(s2)[i]);
}

// =====================================================================
// fp16 tensor GEMM (TN): C[M,N] = A[M,K]*B[N,K]^T, fp16 in, f32 acc.
// Block 128x128x64, 8 warps (2x4), warp tile 64x32 via m16n8k16.
// 3-stage cp.async pipeline, padded 144B SMEM rows, 2 CTA/SM.
// EPI: 0 plain f32, 1 softplus(v+bias[n]) f32, 2 fp16-only store.
// GN guards B rows (N=96). SPLITK via blockIdx.z.
// =====================================================================
constexpr int HROW  = 144;                  // bytes per SMEM row (64 fp16 + 16 pad)
constexpr int HASTG = 128 * HROW;           // 18432 B per operand stage
constexpr int HSTG  = 2 * HASTG;            // 36864 B per stage
constexpr int HSMEM = 3 * HSTG;             // 110592 B

template<int EPI, bool GN, bool SPLITK>
__global__ __launch_bounds__(256, 2)
void h_gemm(const __half* __restrict__ A, int lda,
            const __half* __restrict__ Bw, int ldb,
            float* __restrict__ C, int ldc,
            int K, int N, const float* __restrict__ bias)
{
    extern __shared__ __align__(16) char smraw[];
    const uint32_t sbase = (uint32_t)__cvta_generic_to_shared(smraw);

    if (SPLITK) {
        const size_t kz = (size_t)blockIdx.z;
        A  += kz * K;
        Bw += kz * K;
        C  += kz * (size_t)gridDim.y * 128 * ldc;
    }

    const int tid  = threadIdx.x;
    const int warp = tid >> 5;
    const int lane = tid & 31;
    const int g    = lane >> 2;
    const int t4   = lane & 3;
    const int mw   = (warp >> 2) * 64;
    const int nw   = (warp & 3) * 32;

    const __half* Ab = A  + (size_t)blockIdx.y * 128 * lda;
    const __half* Bb = Bw + (size_t)blockIdx.x * 128 * ldb;
    const int nBase = blockIdx.x * 128;
    const int nt = K / 64;

    const int q  = lane >> 3;
    const int rr = lane & 7;
    const int lmRow = (q & 1) * 8 + rr;
    const int lmCol = (q >> 1) * 16;

    int cr[4], cc[4];
    #pragma unroll
    for (int u = 0; u < 4; ++u) { int idx = tid + u * 256; cr[u] = idx >> 3; cc[u] = idx & 7; }

    auto loadStage = [&](int t, int s) {
        const int k0 = t * 64;
        const uint32_t aS = sbase + s * HSTG;
        const uint32_t bS = aS + HASTG;
        #pragma unroll
        for (int u = 0; u < 4; ++u) {
            const __half* src = Ab + (size_t)cr[u] * lda + k0 + cc[u] * 8;
            uint32_t dst = aS + (uint32_t)(cr[u] * HROW + cc[u] * 16);
            asm volatile("cp.async.cg.shared.global [%0], [%1], 16;" :: "r"(dst), "l"(src));
        }
        #pragma unroll
        for (int u = 0; u < 4; ++u) {
            uint32_t dst = bS + (uint32_t)(cr[u] * HROW + cc[u] * 16);
            if (GN) {
                const bool ok = (nBase + cr[u]) < N;
                const __half* src = Bb + (size_t)(ok ? cr[u] : 0) * ldb + k0 + cc[u] * 8;
                const int sz = ok ? 16 : 0;
                asm volatile("cp.async.cg.shared.global [%0], [%1], 16, %2;"
                             :: "r"(dst), "l"(src), "r"(sz));
            } else {
                const __half* src = Bb + (size_t)cr[u] * ldb + k0 + cc[u] * 8;
                asm volatile("cp.async.cg.shared.global [%0], [%1], 16;" :: "r"(dst), "l"(src));
            }
        }
    };

    float acc[4][4][4];
    #pragma unroll
    for (int i = 0; i < 4; ++i)
        #pragma unroll
        for (int j = 0; j < 4; ++j)
            #pragma unroll
            for (int r = 0; r < 4; ++r) acc[i][j][r] = 0.f;

    #pragma unroll
    for (int t = 0; t < 2; ++t) {
        if (t < nt) loadStage(t, t);
        asm volatile("cp.async.commit_group;");
    }

    for (int t = 0; t < nt; ++t) {
        asm volatile("cp.async.wait_group 1;");
        __syncthreads();
        if (t + 2 < nt) loadStage(t + 2, (t + 2) % 3);
        asm volatile("cp.async.commit_group;");

        const int s = t % 3;
        const uint32_t aS = sbase + s * HSTG;
        const uint32_t bS = aS + HASTG;

        #pragma unroll
        for (int kk = 0; kk < 4; ++kk) {
            uint32_t af[4][4], bf[4][2];
            #pragma unroll
            for (int i = 0; i < 4; ++i) {
                const uint32_t ad = aS + (uint32_t)((mw + i * 16 + lmRow) * HROW + kk * 32 + lmCol);
                asm volatile("ldmatrix.sync.aligned.m8n8.x4.shared.b16 {%0,%1,%2,%3}, [%4];"
                    : "=r"(af[i][0]), "=r"(af[i][1]), "=r"(af[i][2]), "=r"(af[i][3])
                    : "r"(ad));
            }
            #pragma unroll
            for (int jj = 0; jj < 2; ++jj) {
                const uint32_t bd = bS + (uint32_t)((nw + jj * 16 + lmRow) * HROW + kk * 32 + lmCol);
                asm volatile("ldmatrix.sync.aligned.m8n8.x4.shared.b16 {%0,%1,%2,%3}, [%4];"
                    : "=r"(bf[2*jj][0]), "=r"(bf[2*jj+1][0]), "=r"(bf[2*jj][1]), "=r"(bf[2*jj+1][1])
                    : "r"(bd));
            }
            #pragma unroll
            for (int i = 0; i < 4; ++i)
                #pragma unroll
                for (int j = 0; j < 4; ++j)
                    mma_f16(acc[i][j], af[i], bf[j]);
        }
    }

    // ---- epilogue ----
    #pragma unroll
    for (int i = 0; i < 4; ++i) {
        const int m = blockIdx.y * 128 + mw + i * 16 + g;
        #pragma unroll
        for (int j = 0; j < 4; ++j) {
            const int n = nBase + nw + j * 8 + t4 * 2;
            if (GN && n + 2 > N) continue;
            float v0 = acc[i][j][0], v1 = acc[i][j][1];
            float v2 = acc[i][j][2], v3 = acc[i][j][3];
            if (EPI == 1) {
                const float b0v = bias[n], b1v = bias[n + 1];
                v0 = softplus_(v0 + b0v);
                v1 = softplus_(v1 + b1v);
                v2 = softplus_(v2 + b0v);
                v3 = softplus_(v3 + b1v);
            }
            if (EPI == 2) {
                __half* Ch = reinterpret_cast<__half*>(C);
                *reinterpret_cast<__half2*>(&Ch[(size_t)m * ldc + n]) =
                    __floats2half2_rn(v0, v1);
                *reinterpret_cast<__half2*>(&Ch[(size_t)(m + 8) * ldc + n]) =
                    __floats2half2_rn(v2, v3);
            } else {
                *reinterpret_cast<float2*>(&C[(size_t)m * ldc + n])       = make_float2(v0, v1);
                *reinterpret_cast<float2*>(&C[(size_t)(m + 8) * ldc + n]) = make_float2(v2, v3);
            }
        }
    }
}

// =====================================================================
// split-K reduction for x_dbl: sums KSPL partials -> f32 + fp16
// =====================================================================
__global__ __launch_bounds__(256)
void reduce_xdbl(int n4)
{
    const int i = blockIdx.x * blockDim.x + threadIdx.x;
    if (i >= n4) return;
    const size_t stride4 = (size_t)BATCH * L * XD / 4;
    const float4* p = reinterpret_cast<const float4*>(g_xdbl_p);
    float4 a = p[i], b = p[i + stride4], c = p[i + 2 * stride4], d = p[i + 3 * stride4];
    float4 s;
    s.x = (a.x + b.x) + (c.x + d.x);
    s.y = (a.y + b.y) + (c.y + d.y);
    s.z = (a.z + b.z) + (c.z + d.z);
    s.w = (a.w + b.w) + (c.w + d.w);
    reinterpret_cast<float4*>(g_xdbl)[i] = s;
    reinterpret_cast<uint2*>(g_xdblh)[i] = cvt4(s);
}

// =====================================================================
// Dual dilated causal depthwise conv + silu + softmax gate.
// Reads fp16 x from g_xz_h; writes f32 (scan) + fp16 (xdbl GEMM).
// =====================================================================
__global__ __launch_bounds__(256)
void conv_kernel(const float* __restrict__ w1, const float* __restrict__ b1,
                 const float* __restrict__ w2, const float* __restrict__ b2,
                 const float* __restrict__ gates)
{
    const int tid = blockIdx.x * blockDim.x + threadIdx.x;
    const int d    = tid % DI;
    const int rest = tid / DI;
    const int lc   = rest % (L / 16);
    const int b    = rest / (L / 16);
    const int l0   = lc * 16;

    const __half* xp = g_xz_h + (size_t)b * L * E2 + d;
    const size_t obase = (size_t)b * L * DI + d;

    const float w10 = w1[d*4+0], w11 = w1[d*4+1], w12 = w1[d*4+2], w13 = w1[d*4+3];
    const float w20 = w2[d*4+0], w21 = w2[d*4+1], w22 = w2[d*4+2], w23 = w2[d*4+3];
    const float b1v = b1[d], b2v = b2[d];
    const float e0 = __expf(gates[0]), e1 = __expf(gates[1]);
    const float gden = 1.f / (e0 + e1);
    const float g0 = e0 * gden, g1 = e1 * gden;

    float xb[22];
    #pragma unroll
    for (int i = 0; i < 22; ++i) {
        const int l = l0 - 6 + i;
        xb[i] = (l >= 0) ? __half2float(xp[(size_t)l * E2]) : 0.f;
    }
    #pragma unroll
    for (int i = 0; i < 16; ++i) {
        const float x0  = xb[i+6], xm1 = xb[i+5], xm2 = xb[i+4];
        const float xm3 = xb[i+3], xm4 = xb[i+2], xm6 = xb[i+0];
        const float c1 = fmaf(w13, x0, fmaf(w12, xm1, fmaf(w11, xm2, fmaf(w10, xm3, b1v))));
        const float c2 = fmaf(w23, x0, fmaf(w22, xm2, fmaf(w21, xm4, fmaf(w20, xm6, b2v))));
        const float s1 = c1 * sigmoidf_(c1);
        const float s2 = c2 * sigmoidf_(c2);
        const float v  = fmaf(g0, s1, g1 * s2);
        g_xc  [obase + (size_t)(l0 + i) * DI] = v;
        g_xc_h[obase + (size_t)(l0 + i) * DI] = __float2half_rn(v);
    }
}

// =====================================================================
// Selective scan + D-skip + silu(z) gate, SMEM-staged operands.
// 8 lanes per channel, 2 states per lane (n, n+8); warp = 4 channels.
// z read from fp16 g_xz_h.
// =====================================================================
constexpr int CH  = 16;   // timesteps per chunk
constexpr int CPB = 32;   // channels per block
__global__ __launch_bounds__(256)
void scan_kernel(const float* __restrict__ A_log, const float* __restrict__ D_param)
{
    __shared__ float sd [2][CH][CPB];   // delta
    __shared__ float sxv[2][CH][CPB];   // xc
    __shared__ float szv[2][CH][CPB];   // z
    __shared__ float sbc[2][CH][32];    // B(16) | C(16), channel-independent

    const int tid   = threadIdx.x;
    const int warp  = tid >> 5;
    const int lane  = tid & 31;
    const int grp   = lane >> 3;
    const int n     = lane & 7;
    const int ch    = warp * 4 + grp;
    const int blk   = blockIdx.x;
    const int b     = blk >> 6;
    const int dbase = (blk & 63) * CPB;
    const int d     = dbase + ch;

    const float LG2E = 1.4426950408889634f;
    const float Ac0 = -__expf(A_log[d * DS + n])     * LG2E;
    const float Ac1 = -__expf(A_log[d * DS + n + 8]) * LG2E;
    const float Dv  = D_param[d];

    const int srow = tid >> 4;
    const int sc2  = (tid & 15) * 2;
    const size_t mb = (size_t)b * L;

    auto stage = [&](int c, int buf) {
        const int l = c * CH + srow;
        float2 t;
        t = *reinterpret_cast<const float2*>(g_delta + (mb + l) * DI + dbase + sc2);
        sd [buf][srow][sc2] = t.x; sd [buf][srow][sc2 + 1] = t.y;
        t = *reinterpret_cast<const float2*>(g_xc + (mb + l) * DI + dbase + sc2);
        sxv[buf][srow][sc2] = t.x; sxv[buf][srow][sc2 + 1] = t.y;
        const __half2 zh = *reinterpret_cast<const __half2*>(
            g_xz_h + (mb + l) * E2 + DI + dbase + sc2);
        t = __half22float2(zh);
        szv[buf][srow][sc2] = t.x; szv[buf][srow][sc2 + 1] = t.y;
        t = *reinterpret_cast<const float2*>(g_xdbl + (mb + l) * XD + DR + sc2);
        sbc[buf][srow][sc2] = t.x; sbc[buf][srow][sc2 + 1] = t.y;
    };

    stage(0, 0);
    __syncthreads();

    __half* yp = g_y_h + mb * DI + d;
    float h0 = 0.f, h1 = 0.f;

    for (int c = 0; c < L / CH; ++c) {
        const int buf = c & 1;
        if (c + 1 < L / CH) stage(c + 1, buf ^ 1);

        const int lbase = c * CH;
        #pragma unroll
        for (int i = 0; i < CH; ++i) {
            const float dlt = sd [buf][i][ch];
            const float xv  = sxv[buf][i][ch];
            const float zv  = szv[buf][i][ch];
            const float B0  = sbc[buf][i][n];
            const float B1  = sbc[buf][i][n + 8];
            const float C0  = sbc[buf][i][16 + n];
            const float C1  = sbc[buf][i][24 + n];

            const float dA0 = ex2_(dlt * Ac0);
            const float dA1 = ex2_(dlt * Ac1);
            const float tt  = dlt * xv;
            h0 = fmaf(h0, dA0, tt * B0);
            h1 = fmaf(h1, dA1, tt * B1);

            float v = fmaf(h1, C1, h0 * C0);
            v += __shfl_xor_sync(FULLMASK, v, 1);
            v += __shfl_xor_sync(FULLMASK, v, 2);
            v += __shfl_xor_sync(FULLMASK, v, 4);

            if (n == 0) {
                const float y = fmaf(Dv, xv, v);
                yp[(size_t)(lbase + i) * DI] = __float2half_rn(y * (zv * sigmoidf_(zv)));
            }
        }
        __syncthreads();
    }
}

// =====================================================================
extern "C" void kernel_launch(void* const* d_in, const int* in_sizes, int n_in,
                              void* d_out, int out_size)
{
    const float* hidden     = (const float*)d_in[0];
    const float* W_in       = (const float*)d_in[1];
    const float* conv_w1    = (const float*)d_in[2];
    const float* conv_b1    = (const float*)d_in[3];
    const float* conv_w2    = (const float*)d_in[4];
    const float* conv_b2    = (const float*)d_in[5];
    const float* conv_gates = (const float*)d_in[6];
    const float* W_x        = (const float*)d_in[7];
    const float* W_dt       = (const float*)d_in[8];
    const float* b_dt       = (const float*)d_in[9];
    const float* A_log      = (const float*)d_in[10];
    const float* D_param    = (const float*)d_in[11];
    const float* W_out      = (const float*)d_in[12];
    float*       out        = (float*)d_out;

    float  *p_xdbl_p, *p_delta;
    __half *p_xzh, *p_xch, *p_xdblh, *p_yh, *p_h, *p_win, *p_wx, *p_wdt, *p_wout;
    cudaGetSymbolAddress((void**)&p_xzh,    g_xz_h);
    cudaGetSymbolAddress((void**)&p_xdbl_p, g_xdbl_p);
    cudaGetSymbolAddress((void**)&p_delta,  g_delta);
    cudaGetSymbolAddress((void**)&p_xch,    g_xc_h);
    cudaGetSymbolAddress((void**)&p_xdblh,  g_xdblh);
    cudaGetSymbolAddress((void**)&p_yh,     g_y_h);
    cudaGetSymbolAddress((void**)&p_h,      g_h_h);
    cudaGetSymbolAddress((void**)&p_win,    g_win_h);
    cudaGetSymbolAddress((void**)&p_wx,     g_wx_h);
    cudaGetSymbolAddress((void**)&p_wdt,    g_wdt_h);
    cudaGetSymbolAddress((void**)&p_wout,   g_wout_h);

    static bool attr_done = false;
    if (!attr_done) {
        cudaFuncSetAttribute((const void*)h_gemm<0,false,false>,
                             cudaFuncAttributeMaxDynamicSharedMemorySize, HSMEM);
        cudaFuncSetAttribute((const void*)h_gemm<1,false,false>,
                             cudaFuncAttributeMaxDynamicSharedMemorySize, HSMEM);
        cudaFuncSetAttribute((const void*)h_gemm<2,false,false>,
                             cudaFuncAttributeMaxDynamicSharedMemorySize, HSMEM);
        cudaFuncSetAttribute((const void*)h_gemm<0,true,true>,
                             cudaFuncAttributeMaxDynamicSharedMemorySize, HSMEM);
        attr_done = true;
    }

    const int M = BATCH * L;   // 8192

    // [0] cvt hidden, [1] cvt W_in, [2] fused cvt of W_out/W_x/W_dt
    {
        int n4h = (int)((size_t)BATCH * L * DM / 4);
        cvt_f16<<<(n4h + 255) / 256, 256>>>(hidden, p_h, n4h);
        int n4w = (int)((size_t)E2 * DM / 4);
        cvt_f16<<<(n4w + 255) / 256, 256>>>(W_in, p_win, n4w);
        int n0 = (int)((size_t)DM * DI / 4);
        int n1 = (int)((size_t)XD * DI / 4);
        int n2 = (int)((size_t)DI * DR / 4);
        cvt_f16x3<<<(n0 + n1 + n2 + 255) / 256, 256>>>(
            W_out, p_wout, n0, W_x, p_wx, n1, W_dt, p_wdt, n2);
    }

    // [3] in-proj: (M=8192, N=4096, K=1024), fp16-only output (EPI=2)
    h_gemm<2,false,false><<<dim3(E2/128, M/128), 256, HSMEM>>>(
        p_h, DM, p_win, DM, (float*)p_xzh, E2, DM, E2, nullptr);

    // [4] dwconv + silu + gate -> g_xc (f32) + g_xc_h (fp16)
    conv_kernel<<<(BATCH * (L/16) * DI) / 256, 256>>>(
        conv_w1, conv_b1, conv_w2, conv_b2, conv_gates);

    // [5] x_dbl split-K: (M=8192, N=96, K=2048/4 per slice)
    h_gemm<0,true,true><<<dim3(1, M/128, KSPL), 256, HSMEM>>>(
        p_xch, DI, p_wx, DI, p_xdbl_p, XD, DI / KSPL, XD, nullptr);

    // [6] reduce partials -> g_xdbl (f32) + g_xdblh (fp16)
    {
        int n4 = (int)((size_t)BATCH * L * XD / 4);
        reduce_xdbl<<<(n4 + 255) / 256, 256>>>(n4);
    }

    // [7] delta = softplus(dt_low . W_dt^T + b_dt): (M=8192, N=2048, K=64)
    h_gemm<1,false,false><<<dim3(DI/128, M/128), 256, HSMEM>>>(
        p_xdblh, XD, p_wdt, DR, p_delta, DI, DR, DI, b_dt);

    // [8] selective scan -> g_y_h (fp16)
    scan_kernel<<<BATCH * (DI / CPB), 256>>>(A_log, D_param);

    // [9] out-proj: (M=8192, N=1024, K=2048)
    h_gemm<0,false,false><<<dim3(DM/128, M/128), 256, HSMEM>>>(
        p_yh, DI, p_wout, DI, out, DM, DI, DM, nullptr);
}

// round 16
// speedup vs baseline: 1.0422x; 1.0100x over previous
#include <cuda_runtime.h>
#include <cuda_fp16.h>
#include <math.h>
#include <stdint.h>

#define FULLMASK 0xffffffffu

constexpr int BATCH = 4, L = 2048, DM = 1024, DI = 2048, E2 = 4096;
constexpr int DR = 64, DS = 16, XD = 96; // XD = DR + 2*DS
constexpr int KSPL = 4;                  // split-K factor for x_dbl GEMM

// ---- scratch (device globals; no runtime allocation) ----
__device__ __half g_xz_h [(size_t)BATCH * L * E2];   // in-proj out fp16: x | z
__device__ __half g_xc_h [(size_t)BATCH * L * DI];   // conv out fp16 (scan + xdbl GEMM A)
__device__ float  g_xdbl [(size_t)BATCH * L * XD];   // dt_low|B|C f32 (scan B/C)
__device__ __half g_xdblh[(size_t)BATCH * L * XD];   // fp16 copy (dt GEMM A)
__device__ float  g_xdbl_p[(size_t)KSPL * BATCH * L * XD]; // split-K partials
__device__ __half g_delta_h[(size_t)BATCH * L * DI]; // softplus(dt+b_dt) fp16 (scan)
__device__ __half g_y_h  [(size_t)BATCH * L * DI];   // gated scan out fp16
// fp16 copies of external operands
__device__ __half g_h_h   [(size_t)BATCH * L * DM];
__device__ __half g_win_h [(size_t)E2 * DM];
__device__ __half g_wx_h  [(size_t)XD * DI];
__device__ __half g_wdt_h [(size_t)DI * DR];
__device__ __half g_wout_h[(size_t)DM * DI];

__device__ __forceinline__ float sigmoidf_(float x) { return 1.f / (1.f + __expf(-x)); }

__device__ __forceinline__ float ex2_(float x) {
    float r; asm("ex2.approx.f32 %0, %1;" : "=f"(r) : "f"(x)); return r;
}
__device__ __forceinline__ float lg2_(float x) {
    float r; asm("lg2.approx.f32 %0, %1;" : "=f"(r) : "f"(x)); return r;
}
// softplus via MUFU: log(1+e^v) = ln2 * lg2(1 + 2^(v*log2e))
__device__ __forceinline__ float softplus_(float v) {
    const float LG2E = 1.4426950408889634f, LN2 = 0.6931471805599453f;
    return (v > 20.f) ? v : LN2 * lg2_(1.f + ex2_(v * LG2E));
}

__device__ __forceinline__ void mma_f16(float c[4], const uint32_t a[4], const uint32_t b[2]) {
    asm volatile(
        "mma.sync.aligned.m16n8k16.row.col.f32.f16.f16.f32 "
        "{%0,%1,%2,%3}, {%4,%5,%6,%7}, {%8,%9}, {%0,%1,%2,%3};"
        : "+f"(c[0]), "+f"(c[1]), "+f"(c[2]), "+f"(c[3])
        : "r"(a[0]), "r"(a[1]), "r"(a[2]), "r"(a[3]), "r"(b[0]), "r"(b[1]));
}

__device__ __forceinline__ uint2 cvt4(float4 v) {
    __half2 h0 = __floats2half2_rn(v.x, v.y);
    __half2 h1 = __floats2half2_rn(v.z, v.w);
    uint2 pk;
    pk.x = *reinterpret_cast<uint32_t*>(&h0);
    pk.y = *reinterpret_cast<uint32_t*>(&h1);
    return pk;
}

// =====================================================================
// Fused f32 -> f16 conversion of all 5 external operands (one launch)
// =====================================================================
__global__ __launch_bounds__(256)
void cvt_f16x5(const float* __restrict__ s0, __half* __restrict__ d0, int n0,
               const float* __restrict__ s1, __half* __restrict__ d1, int n1,
               const float* __restrict__ s2, __half* __restrict__ d2, int n2,
               const float* __restrict__ s3, __half* __restrict__ d3, int n3,
               const float* __restrict__ s4, __half* __restrict__ d4, int n4)
{
    int i = blockIdx.x * blockDim.x + threadIdx.x;
    if (i < n0) { reinterpret_cast<uint2*>(d0)[i] = cvt4(reinterpret_cast<const float4*>(s0)[i]); return; }
    i -= n0;
    if (i < n1) { reinterpret_cast<uint2*>(d1)[i] = cvt4(reinterpret_cast<const float4*>(s1)[i]); return; }
    i -= n1;
    if (i < n2) { reinterpret_cast<uint2*>(d2)[i] = cvt4(reinterpret_cast<const float4*>(s2)[i]); return; }
    i -= n2;
    if (i < n3) { reinterpret_cast<uint2*>(d3)[i] = cvt4(reinterpret_cast<const float4*>(s3)[i]); return; }
    i -= n3;
    if (i < n4) { reinterpret_cast<uint2*>(d4)[i] = cvt4(reinterpret_cast<const float4*>(s4)[i]); }
}

// =====================================================================
// fp16 tensor GEMM (TN): C[M,N] = A[M,K]*B[N,K]^T, fp16 in, f32 acc.
// Block 128x128x64, 8 warps (2x4), warp tile 64x32 via m16n8k16.
// 3-stage cp.async pipeline, padded 144B SMEM rows, 2 CTA/SM.
// EPI: 0 plain f32, 1 softplus f32, 2 fp16 plain, 3 softplus fp16.
// GN guards B rows (N=96). SPLITK via blockIdx.z.
// =====================================================================
constexpr int HROW  = 144;                  // bytes per SMEM row (64 fp16 + 16 pad)
constexpr int HASTG = 128 * HROW;           // 18432 B per operand stage
constexpr int HSTG  = 2 * HASTG;            // 36864 B per stage
constexpr int HSMEM = 3 * HSTG;             // 110592 B

template<int EPI, bool GN, bool SPLITK>
__global__ __launch_bounds__(256, 2)
void h_gemm(const __half* __restrict__ A, int lda,
            const __half* __restrict__ Bw, int ldb,
            float* __restrict__ C, int ldc,
            int K, int N, const float* __restrict__ bias)
{
    extern __shared__ __align__(16) char smraw[];
    const uint32_t sbase = (uint32_t)__cvta_generic_to_shared(smraw);

    if (SPLITK) {
        const size_t kz = (size_t)blockIdx.z;
        A  += kz * K;
        Bw += kz * K;
        C  += kz * (size_t)gridDim.y * 128 * ldc;
    }

    const int tid  = threadIdx.x;
    const int warp = tid >> 5;
    const int lane = tid & 31;
    const int g    = lane >> 2;
    const int t4   = lane & 3;
    const int mw   = (warp >> 2) * 64;
    const int nw   = (warp & 3) * 32;

    const __half* Ab = A  + (size_t)blockIdx.y * 128 * lda;
    const __half* Bb = Bw + (size_t)blockIdx.x * 128 * ldb;
    const int nBase = blockIdx.x * 128;
    const int nt = K / 64;

    const int q  = lane >> 3;
    const int rr = lane & 7;
    const int lmRow = (q & 1) * 8 + rr;
    const int lmCol = (q >> 1) * 16;

    int cr[4], cc[4];
    #pragma unroll
    for (int u = 0; u < 4; ++u) { int idx = tid + u * 256; cr[u] = idx >> 3; cc[u] = idx & 7; }

    auto loadStage = [&](int t, int s) {
        const int k0 = t * 64;
        const uint32_t aS = sbase + s * HSTG;
        const uint32_t bS = aS + HASTG;
        #pragma unroll
        for (int u = 0; u < 4; ++u) {
            const __half* src = Ab + (size_t)cr[u] * lda + k0 + cc[u] * 8;
            uint32_t dst = aS + (uint32_t)(cr[u] * HROW + cc[u] * 16);
            asm volatile("cp.async.cg.shared.global [%0], [%1], 16;" :: "r"(dst), "l"(src));
        }
        #pragma unroll
        for (int u = 0; u < 4; ++u) {
            uint32_t dst = bS + (uint32_t)(cr[u] * HROW + cc[u] * 16);
            if (GN) {
                const bool ok = (nBase + cr[u]) < N;
                const __half* src = Bb + (size_t)(ok ? cr[u] : 0) * ldb + k0 + cc[u] * 8;
                const int sz = ok ? 16 : 0;
                asm volatile("cp.async.cg.shared.global [%0], [%1], 16, %2;"
                             :: "r"(dst), "l"(src), "r"(sz));
            } else {
                const __half* src = Bb + (size_t)cr[u] * ldb + k0 + cc[u] * 8;
                asm volatile("cp.async.cg.shared.global [%0], [%1], 16;" :: "r"(dst), "l"(src));
            }
        }
    };

    float acc[4][4][4];
    #pragma unroll
    for (int i = 0; i < 4; ++i)
        #pragma unroll
        for (int j = 0; j < 4; ++j)
            #pragma unroll
            for (int r = 0; r < 4; ++r) acc[i][j][r] = 0.f;

    #pragma unroll
    for (int t = 0; t < 2; ++t) {
        if (t < nt) loadStage(t, t);
        asm volatile("cp.async.commit_group;");
    }

    for (int t = 0; t < nt; ++t) {
        asm volatile("cp.async.wait_group 1;");
        __syncthreads();
        if (t + 2 < nt) loadStage(t + 2, (t + 2) % 3);
        asm volatile("cp.async.commit_group;");

        const int s = t % 3;
        const uint32_t aS = sbase + s * HSTG;
        const uint32_t bS = aS + HASTG;

        #pragma unroll
        for (int kk = 0; kk < 4; ++kk) {
            uint32_t af[4][4], bf[4][2];
            #pragma unroll
            for (int i = 0; i < 4; ++i) {
                const uint32_t ad = aS + (uint32_t)((mw + i * 16 + lmRow) * HROW + kk * 32 + lmCol);
                asm volatile("ldmatrix.sync.aligned.m8n8.x4.shared.b16 {%0,%1,%2,%3}, [%4];"
                    : "=r"(af[i][0]), "=r"(af[i][1]), "=r"(af[i][2]), "=r"(af[i][3])
                    : "r"(ad));
            }
            #pragma unroll
            for (int jj = 0; jj < 2; ++jj) {
                const uint32_t bd = bS + (uint32_t)((nw + jj * 16 + lmRow) * HROW + kk * 32 + lmCol);
                asm volatile("ldmatrix.sync.aligned.m8n8.x4.shared.b16 {%0,%1,%2,%3}, [%4];"
                    : "=r"(bf[2*jj][0]), "=r"(bf[2*jj+1][0]), "=r"(bf[2*jj][1]), "=r"(bf[2*jj+1][1])
                    : "r"(bd));
            }
            #pragma unroll
            for (int i = 0; i < 4; ++i)
                #pragma unroll
                for (int j = 0; j < 4; ++j)
                    mma_f16(acc[i][j], af[i], bf[j]);
        }
    }

    // ---- epilogue ----
    #pragma unroll
    for (int i = 0; i < 4; ++i) {
        const int m = blockIdx.y * 128 + mw + i * 16 + g;
        #pragma unroll
        for (int j = 0; j < 4; ++j) {
            const int n = nBase + nw + j * 8 + t4 * 2;
            if (GN && n + 2 > N) continue;
            float v0 = acc[i][j][0], v1 = acc[i][j][1];
            float v2 = acc[i][j][2], v3 = acc[i][j][3];
            if (EPI == 1 || EPI == 3) {
                const float b0v = bias[n], b1v = bias[n + 1];
                v0 = softplus_(v0 + b0v);
                v1 = softplus_(v1 + b1v);
                v2 = softplus_(v2 + b0v);
                v3 = softplus_(v3 + b1v);
            }
            if (EPI == 2 || EPI == 3) {
                __half* Ch = reinterpret_cast<__half*>(C);
                *reinterpret_cast<__half2*>(&Ch[(size_t)m * ldc + n]) =
                    __floats2half2_rn(v0, v1);
                *reinterpret_cast<__half2*>(&Ch[(size_t)(m + 8) * ldc + n]) =
                    __floats2half2_rn(v2, v3);
            } else {
                *reinterpret_cast<float2*>(&C[(size_t)m * ldc + n])       = make_float2(v0, v1);
                *reinterpret_cast<float2*>(&C[(size_t)(m + 8) * ldc + n]) = make_float2(v2, v3);
            }
        }
    }
}

// =====================================================================
// split-K reduction for x_dbl: sums KSPL partials -> f32 + fp16
// =====================================================================
__global__ __launch_bounds__(256)
void reduce_xdbl(int n4)
{
    const int i = blockIdx.x * blockDim.x + threadIdx.x;
    if (i >= n4) return;
    const size_t stride4 = (size_t)BATCH * L * XD / 4;
    const float4* p = reinterpret_cast<const float4*>(g_xdbl_p);
    float4 a = p[i], b = p[i + stride4], c = p[i + 2 * stride4], d = p[i + 3 * stride4];
    float4 s;
    s.x = (a.x + b.x) + (c.x + d.x);
    s.y = (a.y + b.y) + (c.y + d.y);
    s.z = (a.z + b.z) + (c.z + d.z);
    s.w = (a.w + b.w) + (c.w + d.w);
    reinterpret_cast<float4*>(g_xdbl)[i] = s;
    reinterpret_cast<uint2*>(g_xdblh)[i] = cvt4(s);
}

// =====================================================================
// Dual dilated causal depthwise conv + silu + softmax gate.
// Reads fp16 x from g_xz_h; writes fp16 xc only.
// =====================================================================
__global__ __launch_bounds__(256)
void conv_kernel(const float* __restrict__ w1, const float* __restrict__ b1,
                 const float* __restrict__ w2, const float* __restrict__ b2,
                 const float* __restrict__ gates)
{
    const int tid = blockIdx.x * blockDim.x + threadIdx.x;
    const int d    = tid % DI;
    const int rest = tid / DI;
    const int lc   = rest % (L / 16);
    const int b    = rest / (L / 16);
    const int l0   = lc * 16;

    const __half* xp = g_xz_h + (size_t)b * L * E2 + d;
    const size_t obase = (size_t)b * L * DI + d;

    const float w10 = w1[d*4+0], w11 = w1[d*4+1], w12 = w1[d*4+2], w13 = w1[d*4+3];
    const float w20 = w2[d*4+0], w21 = w2[d*4+1], w22 = w2[d*4+2], w23 = w2[d*4+3];
    const float b1v = b1[d], b2v = b2[d];
    const float e0 = __expf(gates[0]), e1 = __expf(gates[1]);
    const float gden = 1.f / (e0 + e1);
    const float g0 = e0 * gden, g1 = e1 * gden;

    float xb[22];
    #pragma unroll
    for (int i = 0; i < 22; ++i) {
        const int l = l0 - 6 + i;
        xb[i] = (l >= 0) ? __half2float(xp[(size_t)l * E2]) : 0.f;
    }
    #pragma unroll
    for (int i = 0; i < 16; ++i) {
        const float x0  = xb[i+6], xm1 = xb[i+5], xm2 = xb[i+4];
        const float xm3 = xb[i+3], xm4 = xb[i+2], xm6 = xb[i+0];
        const float c1 = fmaf(w13, x0, fmaf(w12, xm1, fmaf(w11, xm2, fmaf(w10, xm3, b1v))));
        const float c2 = fmaf(w23, x0, fmaf(w22, xm2, fmaf(w21, xm4, fmaf(w20, xm6, b2v))));
        const float s1 = c1 * sigmoidf_(c1);
        const float s2 = c2 * sigmoidf_(c2);
        const float v  = fmaf(g0, s1, g1 * s2);
        g_xc_h[obase + (size_t)(l0 + i) * DI] = __float2half_rn(v);
    }
}

// =====================================================================
// Selective scan + D-skip + silu(z) gate, SMEM-staged operands.
// 8 lanes per channel, 2 states per lane (n, n+8); warp = 4 channels.
// delta/xc/z read fp16; B/C read f32.
// =====================================================================
constexpr int CH  = 16;   // timesteps per chunk
constexpr int CPB = 32;   // channels per block
__global__ __launch_bounds__(256)
void scan_kernel(const float* __restrict__ A_log, const float* __restrict__ D_param)
{
    __shared__ float sd [2][CH][CPB];   // delta
    __shared__ float sxv[2][CH][CPB];   // xc
    __shared__ float szv[2][CH][CPB];   // z
    __shared__ float sbc[2][CH][32];    // B(16) | C(16), channel-independent

    const int tid   = threadIdx.x;
    const int warp  = tid >> 5;
    const int lane  = tid & 31;
    const int grp   = lane >> 3;
    const int n     = lane & 7;
    const int ch    = warp * 4 + grp;
    const int blk   = blockIdx.x;
    const int b     = blk >> 6;
    const int dbase = (blk & 63) * CPB;
    const int d     = dbase + ch;

    const float LG2E = 1.4426950408889634f;
    const float Ac0 = -__expf(A_log[d * DS + n])     * LG2E;
    const float Ac1 = -__expf(A_log[d * DS + n + 8]) * LG2E;
    const float Dv  = D_param[d];

    const int srow = tid >> 4;
    const int sc2  = (tid & 15) * 2;
    const size_t mb = (size_t)b * L;

    auto stage = [&](int c, int buf) {
        const int l = c * CH + srow;
        float2 t;
        t = __half22float2(*reinterpret_cast<const __half2*>(
            g_delta_h + (mb + l) * DI + dbase + sc2));
        sd [buf][srow][sc2] = t.x; sd [buf][srow][sc2 + 1] = t.y;
        t = __half22float2(*reinterpret_cast<const __half2*>(
            g_xc_h + (mb + l) * DI + dbase + sc2));
        sxv[buf][srow][sc2] = t.x; sxv[buf][srow][sc2 + 1] = t.y;
        t = __half22float2(*reinterpret_cast<const __half2*>(
            g_xz_h + (mb + l) * E2 + DI + dbase + sc2));
        szv[buf][srow][sc2] = t.x; szv[buf][srow][sc2 + 1] = t.y;
        t = *reinterpret_cast<const float2*>(g_xdbl + (mb + l) * XD + DR + sc2);
        sbc[buf][srow][sc2] = t.x; sbc[buf][srow][sc2 + 1] = t.y;
    };

    stage(0, 0);
    __syncthreads();

    __half* yp = g_y_h + mb * DI + d;
    float h0 = 0.f, h1 = 0.f;

    for (int c = 0; c < L / CH; ++c) {
        const int buf = c & 1;
        if (c + 1 < L / CH) stage(c + 1, buf ^ 1);

        const int lbase = c * CH;
        #pragma unroll
        for (int i = 0; i < CH; ++i) {
            const float dlt = sd [buf][i][ch];
            const float xv  = sxv[buf][i][ch];
            const float zv  = szv[buf][i][ch];
            const float B0  = sbc[buf][i][n];
            const float B1  = sbc[buf][i][n + 8];
            const float C0  = sbc[buf][i][16 + n];
            const float C1  = sbc[buf][i][24 + n];

            const float dA0 = ex2_(dlt * Ac0);
            const float dA1 = ex2_(dlt * Ac1);
            const float tt  = dlt * xv;
            h0 = fmaf(h0, dA0, tt * B0);
            h1 = fmaf(h1, dA1, tt * B1);

            float v = fmaf(h1, C1, h0 * C0);
            v += __shfl_xor_sync(FULLMASK, v, 1);
            v += __shfl_xor_sync(FULLMASK, v, 2);
            v += __shfl_xor_sync(FULLMASK, v, 4);

            if (n == 0) {
                const float y = fmaf(Dv, xv, v);
                yp[(size_t)(lbase + i) * DI] = __float2half_rn(y * (zv * sigmoidf_(zv)));
            }
        }
        __syncthreads();
    }
}

// =====================================================================
extern "C" void kernel_launch(void* const* d_in, const int* in_sizes, int n_in,
                              void* d_out, int out_size)
{
    const float* hidden     = (const float*)d_in[0];
    const float* W_in       = (const float*)d_in[1];
    const float* conv_w1    = (const float*)d_in[2];
    const float* conv_b1    = (const float*)d_in[3];
    const float* conv_w2    = (const float*)d_in[4];
    const float* conv_b2    = (const float*)d_in[5];
    const float* conv_gates = (const float*)d_in[6];
    const float* W_x        = (const float*)d_in[7];
    const float* W_dt       = (const float*)d_in[8];
    const float* b_dt       = (const float*)d_in[9];
    const float* A_log      = (const float*)d_in[10];
    const float* D_param    = (const float*)d_in[11];
    const float* W_out      = (const float*)d_in[12];
    float*       out        = (float*)d_out;

    float  *p_xdbl_p;
    __half *p_xzh, *p_xch, *p_xdblh, *p_dlh, *p_yh, *p_h, *p_win, *p_wx, *p_wdt, *p_wout;
    cudaGetSymbolAddress((void**)&p_xzh,    g_xz_h);
    cudaGetSymbolAddress((void**)&p_xdbl_p, g_xdbl_p);
    cudaGetSymbolAddress((void**)&p_dlh,    g_delta_h);
    cudaGetSymbolAddress((void**)&p_xch,    g_xc_h);
    cudaGetSymbolAddress((void**)&p_xdblh,  g_xdblh);
    cudaGetSymbolAddress((void**)&p_yh,     g_y_h);
    cudaGetSymbolAddress((void**)&p_h,      g_h_h);
    cudaGetSymbolAddress((void**)&p_win,    g_win_h);
    cudaGetSymbolAddress((void**)&p_wx,     g_wx_h);
    cudaGetSymbolAddress((void**)&p_wdt,    g_wdt_h);
    cudaGetSymbolAddress((void**)&p_wout,   g_wout_h);

    static bool attr_done = false;
    if (!attr_done) {
        cudaFuncSetAttribute((const void*)h_gemm<0,false,false>,
                             cudaFuncAttributeMaxDynamicSharedMemorySize, HSMEM);
        cudaFuncSetAttribute((const void*)h_gemm<2,false,false>,
                             cudaFuncAttributeMaxDynamicSharedMemorySize, HSMEM);
        cudaFuncSetAttribute((const void*)h_gemm<3,false,false>,
                             cudaFuncAttributeMaxDynamicSharedMemorySize, HSMEM);
        cudaFuncSetAttribute((const void*)h_gemm<0,true,true>,
                             cudaFuncAttributeMaxDynamicSharedMemorySize, HSMEM);
        attr_done = true;
    }

    const int M = BATCH * L;   // 8192

    // [0] fused cvt of all 5 external operands
    {
        int n0 = (int)((size_t)BATCH * L * DM / 4);   // hidden
        int n1 = (int)((size_t)E2 * DM / 4);          // W_in
        int n2 = (int)((size_t)DM * DI / 4);          // W_out
        int n3 = (int)((size_t)XD * DI / 4);          // W_x
        int n4 = (int)((size_t)DI * DR / 4);          // W_dt
        int tot = n0 + n1 + n2 + n3 + n4;
        cvt_f16x5<<<(tot + 255) / 256, 256>>>(
            hidden, p_h, n0, W_in, p_win, n1, W_out, p_wout, n2,
            W_x, p_wx, n3, W_dt, p_wdt, n4);
    }

    // [1] in-proj: (M=8192, N=4096, K=1024), fp16-only output
    h_gemm<2,false,false><<<dim3(E2/128, M/128), 256, HSMEM>>>(
        p_h, DM, p_win, DM, (float*)p_xzh, E2, DM, E2, nullptr);

    // [2] dwconv + silu + gate -> g_xc_h (fp16)
    conv_kernel<<<(BATCH * (L/16) * DI) / 256, 256>>>(
        conv_w1, conv_b1, conv_w2, conv_b2, conv_gates);

    // [3] x_dbl split-K: (M=8192, N=96, K=2048/4 per slice)  <-- profiled slot
    h_gemm<0,true,true><<<dim3(1, M/128, KSPL), 256, HSMEM>>>(
        p_xch, DI, p_wx, DI, p_xdbl_p, XD, DI / KSPL, XD, nullptr);

    // [4] reduce partials -> g_xdbl (f32) + g_xdblh (fp16)
    {
        int n4 = (int)((size_t)BATCH * L * XD / 4);
        reduce_xdbl<<<(n4 + 255) / 256, 256>>>(n4);
    }

    // [5] delta = softplus(dt_low . W_dt^T + b_dt): (M=8192, N=2048, K=64), fp16 out
    h_gemm<3,false,false><<<dim3(DI/128, M/128), 256, HSMEM>>>(
        p_xdblh, XD, p_wdt, DR, (float*)p_dlh, DI, DR, DI, b_dt);

    // [6] selective scan -> g_y_h (fp16)
    scan_kernel<<<BATCH * (DI / CPB), 256>>>(A_log, D_param);

    // [7] out-proj: (M=8192, N=1024, K=2048)
    h_gemm<0,false,false><<<dim3(DM/128, M/128), 256, HSMEM>>>(
        p_yh, DI, p_wout, DI, out, DM, DI, DM, nullptr);
}